// round 10
// baseline (speedup 1.0000x reference)
#include <cuda_runtime.h>
#include <cuda_bf16.h>

// SpatialGNN: 2-layer GATv2, G = 6144 graphs, N=32, C=64, H=4, D=16, E=160.
// R10: degree-sorted node schedule (warps process 4 similar-degree nodes ->
// warp loop trip ~ its own degree, not the max of 4 random), CSR entry
// shrunk to int2{src*XP, ew}, layer-0 bf16 hi/lo writeback packed to STS.128.

#define Bb 16
#define Cc 64
#define Nn 32
#define Kk 16
#define Ll 24
#define Ee 160
#define Hh 4
#define Dd 16
#define NG 2
#define Mm 64         // GEMM rows = NG * Nn
#define KP 72         // bf16 row stride for h and weight tiles
#define XP 68         // fp32 row stride for xl/xr
#define OP 68         // fp32 row stride for hOut
#define NTHREADS 512

// ---- block-invariant precomputed state ----
__device__ __align__(16) __nv_bfloat16 g_w[2][2][2][Cc * KP]; // [layer][hi/lo][mat][co*KP+ci]
__device__ __align__(16) float g_vec[2][5 * Cc];              // [layer][bl|br|We|att|bo]
__device__ __align__(16) int2  g_csr[Ee];                     // {src*XP, ew_bits} grouped by dst (rank order)
__device__ int g_rdeg[Nn], g_roff[Nn], g_perm[Nn];            // per sorted rank

struct __align__(16) Smem {
    __nv_bfloat16 hhi[Mm * KP];
    __nv_bfloat16 hlo[Mm * KP];
    union {
        __nv_bfloat16 w[2][2][Cc * KP];   // [hi/lo][mat]
        float hOut[NG][Nn * OP];          // final-layer fp32 result (aliased)
    };
    float xl[NG][Nn * XP];
    float xr[NG][Nn * XP];
    float vecs[5 * Cc] __attribute__((aligned(16)));
    int2  csrPack[Ee];
    int   rdeg[Nn], roff[Nn], perm[Nn];
};

__global__ void __launch_bounds__(NTHREADS)
gat_setup(const int* __restrict__ ei, const float* __restrict__ ewg,
          const float* __restrict__ Wl, const float* __restrict__ blg,
          const float* __restrict__ Wr, const float* __restrict__ brg,
          const float* __restrict__ Weg, const float* __restrict__ attg,
          const float* __restrict__ bog)
{
    __shared__ int sdst[Ee], ssrc[Ee];
    __shared__ float sew[Ee];
    __shared__ int sdeg[Nn], soff[Nn], sperm[Nn], srank[Nn];
    const int tid = threadIdx.x;

    for (int t = tid; t < 2 * 2 * Cc * Cc; t += NTHREADS) {
        int layer = t >> 13, mat = (t >> 12) & 1, co = (t >> 6) & 63, ci = t & 63;
        const float* W = (mat ? Wr : Wl) + layer * Cc * Cc;
        float wv = W[co * Cc + ci];
        __nv_bfloat16 hi = __float2bfloat16(wv);
        g_w[layer][0][mat][co * KP + ci] = hi;
        g_w[layer][1][mat][co * KP + ci] = __float2bfloat16(wv - __bfloat162float(hi));
    }
    for (int t = tid; t < 2 * 5 * Cc; t += NTHREADS) {
        int layer = t / (5 * Cc), r = t % (5 * Cc), j = r >> 6, c = r & 63;
        const float* p = (j == 0) ? blg : (j == 1) ? brg : (j == 2) ? Weg : (j == 3) ? attg : bog;
        g_vec[layer][r] = p[layer * Cc + c];
    }
    if (tid < Ee) { ssrc[tid] = ei[tid]; sdst[tid] = ei[Ee + tid]; sew[tid] = ewg[tid]; }
    if (tid < Nn) sdeg[tid] = 0;
    __syncthreads();
    if (tid < Ee) atomicAdd(&sdeg[sdst[tid]], 1);
    __syncthreads();
    if (tid == 0) {
        // sort nodes by degree (descending, stable) -> perm[rank] = node
        for (int r = 0; r < Nn; r++) sperm[r] = r;
        for (int i = 1; i < Nn; i++) {
            int v = sperm[i], dv = sdeg[v], j = i - 1;
            while (j >= 0 && sdeg[sperm[j]] < dv) { sperm[j + 1] = sperm[j]; j--; }
            sperm[j + 1] = v;
        }
        // CSR offsets laid out in RANK order
        int a = 0;
        for (int r = 0; r < Nn; r++) {
            int n = sperm[r];
            srank[n] = r;
            soff[r] = a;                    // offset for rank r
            g_roff[r] = a;
            g_rdeg[r] = sdeg[n];
            g_perm[r] = n;
            a += sdeg[n];
        }
    }
    __syncthreads();
    if (tid < Ee) {
        int n = sdst[tid], rank = 0;
        for (int e2 = 0; e2 < tid; e2++) rank += (sdst[e2] == n);
        g_csr[soff[srank[n]] + rank] = make_int2(ssrc[tid] * XP, __float_as_int(sew[tid]));
    }
}

__device__ __forceinline__ void mma16816(float* d, const unsigned* a, const unsigned* b) {
    asm volatile(
        "mma.sync.aligned.m16n8k16.row.col.f32.bf16.bf16.f32 "
        "{%0,%1,%2,%3}, {%4,%5,%6,%7}, {%8,%9}, {%0,%1,%2,%3};"
        : "+f"(d[0]), "+f"(d[1]), "+f"(d[2]), "+f"(d[3])
        : "r"(a[0]), "r"(a[1]), "r"(a[2]), "r"(a[3]), "r"(b[0]), "r"(b[1]));
}

__device__ __forceinline__ void ldsm_x4(unsigned* r, unsigned addr) {
    asm volatile("ldmatrix.sync.aligned.m8n8.x4.shared.b16 {%0,%1,%2,%3}, [%4];"
        : "=r"(r[0]), "=r"(r[1]), "=r"(r[2]), "=r"(r[3]) : "r"(addr));
}

__device__ __forceinline__ unsigned cvta_s(const void* p) {
    return (unsigned)__cvta_generic_to_shared(p);
}

__device__ __forceinline__ unsigned pack_bf16(float lo, float hi) {
    __nv_bfloat162 p = __floats2bfloat162_rn(lo, hi);
    return *reinterpret_cast<unsigned*>(&p);
}

__global__ void __launch_bounds__(NTHREADS, 2)
gat_fused(const float* __restrict__ x, float* __restrict__ out)
{
    extern __shared__ char smem_raw[];
    Smem* s = reinterpret_cast<Smem*>(smem_raw);
    const int tid = threadIdx.x;
    const int bk = blockIdx.x / (Ll / NG);
    const int lg = blockIdx.x % (Ll / NG);
    const int b  = bk >> 4;
    const int k  = bk & 15;
    const int l0 = lg * NG;

    // ---- load h and convert to bf16 hi/lo ----
    const float* xb = x + ((size_t)b * Cc * Nn) * (Kk * Ll) + (size_t)k * Ll + l0;
    for (int i2 = tid; i2 < Cc * Nn; i2 += NTHREADS) {
        int c = i2 >> 5, n = i2 & 31;
        float2 v = *reinterpret_cast<const float2*>(xb + ((size_t)c * Nn + n) * (Kk * Ll));
        float vv[2] = {v.x, v.y};
        #pragma unroll
        for (int gp = 0; gp < NG; gp++) {
            int o = (gp * Nn + n) * KP + c;
            __nv_bfloat16 hi = __float2bfloat16(vv[gp]);
            s->hhi[o] = hi;
            s->hlo[o] = __float2bfloat16(vv[gp] - __bfloat162float(hi));
        }
    }
    for (int e = tid; e < Ee; e += NTHREADS) s->csrPack[e] = g_csr[e];
    if (tid < Nn) {
        s->rdeg[tid] = g_rdeg[tid];
        s->roff[tid] = g_roff[tid];
        s->perm[tid] = g_perm[tid];
    }

    for (int layer = 0; layer < 2; layer++) {
        __syncthreads();

        // ---- stage weights: bulk contiguous copy ----
        {
            const uint4* wsrc = reinterpret_cast<const uint4*>(g_w[layer]);
            uint4* wdst = reinterpret_cast<uint4*>(s->w);
            #pragma unroll
            for (int t = tid; t < (2 * 2 * Cc * KP * 2) / 16; t += NTHREADS)
                wdst[t] = wsrc[t];
            if (tid < 5 * Cc) s->vecs[tid] = g_vec[layer][tid];
        }
        __syncthreads();

        // ---- tensor-core GEMM via ldmatrix (hi*Whi + hi*Wlo + lo*Whi) ----
        {
            const int w    = tid >> 5;
            const int lane = tid & 31;
            const int gID  = lane >> 2;
            const int tg   = lane & 3;
            const int mat  = w >> 3;           // 0 -> xl, 1 -> xr
            const int mt   = (w >> 1) & 3;
            const int nh   = w & 1;
            const int lr   = lane & 7;
            const int seg  = lane >> 3;
            const int rowA  = mt * 16 + (seg & 1) * 8 + lr;
            const int kOffA = (seg >> 1) * 8;
            const int colB0 = nh * 32 + (seg >> 1) * 8 + lr;
            const int kOffB = (seg & 1) * 8;

            const unsigned hhiB = cvta_s(s->hhi);
            const unsigned hloB = cvta_s(s->hlo);
            const unsigned whiB = cvta_s(s->w[0][mat]);
            const unsigned wloB = cvta_s(s->w[1][mat]);
            const float* bias = s->vecs + mat * Cc;
            float* dst        = mat ? (float*)s->xr : (float*)s->xl;

            float acc[4][4];
            #pragma unroll
            for (int j = 0; j < 4; j++)
                #pragma unroll
                for (int q = 0; q < 4; q++) acc[j][q] = 0.f;

            #pragma unroll
            for (int kk = 0; kk < 4; kk++) {
                const int ka = kk * 16;
                unsigned ah[4], al[4];
                ldsm_x4(ah, hhiB + (unsigned)(rowA * KP + ka + kOffA) * 2);
                ldsm_x4(al, hloB + (unsigned)(rowA * KP + ka + kOffA) * 2);
                #pragma unroll
                for (int jp = 0; jp < 2; jp++) {
                    const int cB = colB0 + jp * 16;
                    unsigned bh[4], blo[4];
                    ldsm_x4(bh,  whiB + (unsigned)(cB * KP + ka + kOffB) * 2);
                    ldsm_x4(blo, wloB + (unsigned)(cB * KP + ka + kOffB) * 2);
                    mma16816(acc[jp * 2],     ah, bh);
                    mma16816(acc[jp * 2],     ah, blo);
                    mma16816(acc[jp * 2],     al, bh);
                    mma16816(acc[jp * 2 + 1], ah, bh + 2);
                    mma16816(acc[jp * 2 + 1], ah, blo + 2);
                    mma16816(acc[jp * 2 + 1], al, bh + 2);
                }
            }
            #pragma unroll
            for (int j = 0; j < 4; j++) {
                const int col = nh * 32 + j * 8 + tg * 2;
                float2 bv = *reinterpret_cast<const float2*>(bias + col);
                int r0 = mt * 16 + gID, r1 = r0 + 8;
                float2 v0 = make_float2(acc[j][0] + bv.x, acc[j][1] + bv.y);
                float2 v1 = make_float2(acc[j][2] + bv.x, acc[j][3] + bv.y);
                *reinterpret_cast<float2*>(dst + (size_t)(r0 >> 5) * (Nn * XP) + (r0 & 31) * XP + col) = v0;
                *reinterpret_cast<float2*>(dst + (size_t)(r1 >> 5) * (Nn * XP) + (r1 & 31) * XP + col) = v1;
            }
        }
        __syncthreads();

        // ---- FUSED edge scores + softmax + aggregation (degree-sorted ranks) ----
        {
            const int lane = tid & 31;
            const int hf = tid & 1;
            const int hd = (tid >> 1) & 3;
            const int nr = (tid >> 3) & 31;      // sorted rank
            const int gp = tid >> 8;
            const int n  = s->perm[nr];          // actual node
            const int base = hd * Dd + hf * 8;
            const float* Wes  = s->vecs + 2 * Cc;
            const float* atts = s->vecs + 3 * Cc;
            float4 we0 = *reinterpret_cast<const float4*>(Wes + base);
            float4 we1 = *reinterpret_cast<const float4*>(Wes + base + 4);
            float4 at0 = *reinterpret_cast<const float4*>(atts + base);
            float4 at1 = *reinterpret_cast<const float4*>(atts + base + 4);
            float4 xr0 = *reinterpret_cast<const float4*>(&s->xr[gp][n * XP + base]);
            float4 xr1 = *reinterpret_cast<const float4*>(&s->xr[gp][n * XP + base + 4]);
            const int dg = s->rdeg[nr], o = s->roff[nr];
            const unsigned pmask = 3u << (lane & 30);
            float4 ac0 = make_float4(0.f, 0.f, 0.f, 0.f);
            float4 ac1 = make_float4(0.f, 0.f, 0.f, 0.f);
            float den = 0.f;
            for (int j = 0; j < dg; j++) {
                int2 ce = s->csrPack[o + j];
                float w = __int_as_float(ce.y);
                const float* xlp = &s->xl[gp][ce.x];
                float4 a0 = *reinterpret_cast<const float4*>(xlp + base);
                float4 a1 = *reinterpret_cast<const float4*>(xlp + base + 4);
                float z, sum = 0.f;
                z = a0.x + xr0.x + w * we0.x; z = fmaxf(z, 0.2f * z); sum = fmaf(z, at0.x, sum);
                z = a0.y + xr0.y + w * we0.y; z = fmaxf(z, 0.2f * z); sum = fmaf(z, at0.y, sum);
                z = a0.z + xr0.z + w * we0.z; z = fmaxf(z, 0.2f * z); sum = fmaf(z, at0.z, sum);
                z = a0.w + xr0.w + w * we0.w; z = fmaxf(z, 0.2f * z); sum = fmaf(z, at0.w, sum);
                z = a1.x + xr1.x + w * we1.x; z = fmaxf(z, 0.2f * z); sum = fmaf(z, at1.x, sum);
                z = a1.y + xr1.y + w * we1.y; z = fmaxf(z, 0.2f * z); sum = fmaf(z, at1.y, sum);
                z = a1.z + xr1.z + w * we1.z; z = fmaxf(z, 0.2f * z); sum = fmaf(z, at1.z, sum);
                z = a1.w + xr1.w + w * we1.w; z = fmaxf(z, 0.2f * z); sum = fmaf(z, at1.w, sum);
                float ex = __expf(sum + __shfl_xor_sync(pmask, sum, 1));
                den += ex;
                ac0.x = fmaf(ex, a0.x, ac0.x); ac0.y = fmaf(ex, a0.y, ac0.y);
                ac0.z = fmaf(ex, a0.z, ac0.z); ac0.w = fmaf(ex, a0.w, ac0.w);
                ac1.x = fmaf(ex, a1.x, ac1.x); ac1.y = fmaf(ex, a1.y, ac1.y);
                ac1.z = fmaf(ex, a1.z, ac1.z); ac1.w = fmaf(ex, a1.w, ac1.w);
            }
            float r = (dg > 0) ? (1.f / den) : 0.f;
            float4 b0 = *reinterpret_cast<const float4*>(s->vecs + 4 * Cc + base);
            float4 b1 = *reinterpret_cast<const float4*>(s->vecs + 4 * Cc + base + 4);
            float v[8] = { fmaf(ac0.x, r, b0.x), fmaf(ac0.y, r, b0.y),
                           fmaf(ac0.z, r, b0.z), fmaf(ac0.w, r, b0.w),
                           fmaf(ac1.x, r, b1.x), fmaf(ac1.y, r, b1.y),
                           fmaf(ac1.z, r, b1.z), fmaf(ac1.w, r, b1.w) };
            if (layer == 0) {
                int oo = (gp * Nn + n) * KP + base;   // 16B-aligned (72n+base ≡ 0 mod 8)
                float f[8];
                #pragma unroll
                for (int q = 0; q < 8; q++) f[q] = fmaxf(v[q], 0.f);
                unsigned hiw[4], low[4];
                #pragma unroll
                for (int q = 0; q < 4; q++) {
                    hiw[q] = pack_bf16(f[2 * q], f[2 * q + 1]);
                    __nv_bfloat162* hp = reinterpret_cast<__nv_bfloat162*>(&hiw[q]);
                    float r0 = f[2 * q]     - __bfloat162float(hp->x);
                    float r1 = f[2 * q + 1] - __bfloat162float(hp->y);
                    low[q] = pack_bf16(r0, r1);
                }
                *reinterpret_cast<uint4*>(&s->hhi[oo]) = make_uint4(hiw[0], hiw[1], hiw[2], hiw[3]);
                *reinterpret_cast<uint4*>(&s->hlo[oo]) = make_uint4(low[0], low[1], low[2], low[3]);
            } else {
                float* q = &s->hOut[gp][n * OP + base];
                *reinterpret_cast<float4*>(q)     = make_float4(v[0], v[1], v[2], v[3]);
                *reinterpret_cast<float4*>(q + 4) = make_float4(v[4], v[5], v[6], v[7]);
            }
        }
    }
    __syncthreads();

    // ---- write output ----
    float* ob = out + ((size_t)b * Cc * Nn) * (Kk * Ll) + (size_t)k * Ll + l0;
    for (int i2 = tid; i2 < Cc * Nn; i2 += NTHREADS) {
        int c = i2 >> 5, n = i2 & 31;
        float2 v = make_float2(s->hOut[0][n * OP + c], s->hOut[1][n * OP + c]);
        *reinterpret_cast<float2*>(ob + ((size_t)c * Nn + n) * (Kk * Ll)) = v;
    }
}

extern "C" void kernel_launch(void* const* d_in, const int* in_sizes, int n_in,
                              void* d_out, int out_size)
{
    const float* x   = (const float*)d_in[0];
    const int*   ei  = (const int*)  d_in[1];
    const float* ewg = (const float*)d_in[2];
    const float* Wl  = (const float*)d_in[3];
    const float* bl  = (const float*)d_in[4];
    const float* Wr  = (const float*)d_in[5];
    const float* br  = (const float*)d_in[6];
    const float* We  = (const float*)d_in[7];
    const float* att = (const float*)d_in[8];
    const float* bo  = (const float*)d_in[9];
    float* out = (float*)d_out;

    (void)in_sizes; (void)n_in; (void)out_size;

    gat_setup<<<1, NTHREADS>>>(ei, ewg, Wl, bl, Wr, br, We, att, bo);

    int smem = (int)sizeof(Smem);
    cudaFuncSetAttribute(gat_fused, cudaFuncAttributeMaxDynamicSharedMemorySize, smem);
    dim3 grid(Bb * Kk * (Ll / NG));   // 3072 blocks, 2 graphs each
    gat_fused<<<grid, NTHREADS, smem>>>(x, out);
}

// round 12
// speedup vs baseline: 1.0671x; 1.0671x over previous
#include <cuda_runtime.h>
#include <cuda_bf16.h>

// SpatialGNN: 2-layer GATv2, G = 6144 graphs, N=32, C=64, H=4, D=16, E=160.
// R12 = R11 with the shuffle-mask deadlock fixed: the butterfly reduction in
// the fused gather spans only the 4-lane group that shares (node, head) --
// mask 0xF << (lane & 28) -- so divergent deg-loop trip counts across the
// warp's two nodes cannot deadlock. Parallel 64-block setup kernel retained.

#define Bb 16
#define Cc 64
#define Nn 32
#define Kk 16
#define Ll 24
#define Ee 160
#define Hh 4
#define Dd 16
#define NG 2
#define Mm 64         // GEMM rows = NG * Nn
#define KP 72         // bf16 row stride for h and weight tiles
#define XP 68         // fp32 row stride for xl/xr
#define OP 68         // fp32 row stride for hOut
#define NTHREADS 512

// ---- block-invariant precomputed state ----
__device__ __align__(16) __nv_bfloat16 g_w[2][2][2][Cc * KP]; // [layer][hi/lo][mat][co*KP+ci]
__device__ __align__(16) float g_vec[2][5 * Cc];              // [layer][bl|br|We|att|bo]
__device__ __align__(16) int2  g_csr[Ee];                     // {src*XP, ew_bits} grouped by dst (rank order)
__device__ int g_rdeg[Nn], g_roff[Nn], g_perm[Nn];            // per sorted rank

struct __align__(16) Smem {
    __nv_bfloat16 hhi[Mm * KP];
    __nv_bfloat16 hlo[Mm * KP];
    union {
        __nv_bfloat16 w[2][2][Cc * KP];   // [hi/lo][mat]
        float hOut[NG][Nn * OP];          // final-layer fp32 result (aliased)
    };
    float xl[NG][Nn * XP];
    float xr[NG][Nn * XP];
    float vecs[5 * Cc] __attribute__((aligned(16)));
    int2  csrPack[Ee];
    int   rdeg[Nn], roff[Nn], perm[Nn];
};

__global__ void __launch_bounds__(256)
gat_setup(const int* __restrict__ ei, const float* __restrict__ ewg,
          const float* __restrict__ Wl, const float* __restrict__ blg,
          const float* __restrict__ Wr, const float* __restrict__ brg,
          const float* __restrict__ Weg, const float* __restrict__ attg,
          const float* __restrict__ bog)
{
    const int tid = threadIdx.x;
    const int gt  = blockIdx.x * 256 + tid;   // 64 blocks * 256 = 16384 = 2*2*64*64

    // weights -> bf16 hi/lo, one element per thread
    {
        int t = gt;
        int layer = t >> 13, mat = (t >> 12) & 1, co = (t >> 6) & 63, ci = t & 63;
        const float* W = (mat ? Wr : Wl) + layer * Cc * Cc;
        float wv = W[co * Cc + ci];
        __nv_bfloat16 hi = __float2bfloat16(wv);
        g_w[layer][0][mat][co * KP + ci] = hi;
        g_w[layer][1][mat][co * KP + ci] = __float2bfloat16(wv - __bfloat162float(hi));
    }

    if (blockIdx.x == 0) {
        __shared__ int sdst[Ee], ssrc[Ee];
        __shared__ float sew[Ee];
        __shared__ int sdeg[Nn], soff[Nn], sperm[Nn], srank[Nn];

        for (int t = tid; t < 2 * 5 * Cc; t += 256) {
            int layer = t / (5 * Cc), r = t % (5 * Cc), j = r >> 6, c = r & 63;
            const float* p = (j == 0) ? blg : (j == 1) ? brg : (j == 2) ? Weg : (j == 3) ? attg : bog;
            g_vec[layer][r] = p[layer * Cc + c];
        }
        if (tid < Ee) { ssrc[tid] = ei[tid]; sdst[tid] = ei[Ee + tid]; sew[tid] = ewg[tid]; }
        if (tid < Nn) sdeg[tid] = 0;
        __syncthreads();
        if (tid < Ee) atomicAdd(&sdeg[sdst[tid]], 1);
        __syncthreads();
        if (tid == 0) {
            for (int r = 0; r < Nn; r++) sperm[r] = r;
            for (int i = 1; i < Nn; i++) {
                int v = sperm[i], dv = sdeg[v], j = i - 1;
                while (j >= 0 && sdeg[sperm[j]] < dv) { sperm[j + 1] = sperm[j]; j--; }
                sperm[j + 1] = v;
            }
            int a = 0;
            for (int r = 0; r < Nn; r++) {
                int n = sperm[r];
                srank[n] = r;
                soff[r] = a;
                g_roff[r] = a;
                g_rdeg[r] = sdeg[n];
                g_perm[r] = n;
                a += sdeg[n];
            }
        }
        __syncthreads();
        if (tid < Ee) {
            int n = sdst[tid], rank = 0;
            for (int e2 = 0; e2 < tid; e2++) rank += (sdst[e2] == n);
            g_csr[soff[srank[n]] + rank] = make_int2(ssrc[tid] * XP, __float_as_int(sew[tid]));
        }
    }
}

__device__ __forceinline__ void mma16816(float* d, const unsigned* a, const unsigned* b) {
    asm volatile(
        "mma.sync.aligned.m16n8k16.row.col.f32.bf16.bf16.f32 "
        "{%0,%1,%2,%3}, {%4,%5,%6,%7}, {%8,%9}, {%0,%1,%2,%3};"
        : "+f"(d[0]), "+f"(d[1]), "+f"(d[2]), "+f"(d[3])
        : "r"(a[0]), "r"(a[1]), "r"(a[2]), "r"(a[3]), "r"(b[0]), "r"(b[1]));
}

__device__ __forceinline__ void ldsm_x4(unsigned* r, unsigned addr) {
    asm volatile("ldmatrix.sync.aligned.m8n8.x4.shared.b16 {%0,%1,%2,%3}, [%4];"
        : "=r"(r[0]), "=r"(r[1]), "=r"(r[2]), "=r"(r[3]) : "r"(addr));
}

__device__ __forceinline__ unsigned cvta_s(const void* p) {
    return (unsigned)__cvta_generic_to_shared(p);
}

__device__ __forceinline__ unsigned pack_bf16(float lo, float hi) {
    __nv_bfloat162 p = __floats2bfloat162_rn(lo, hi);
    return *reinterpret_cast<unsigned*>(&p);
}

__global__ void __launch_bounds__(NTHREADS, 2)
gat_fused(const float* __restrict__ x, float* __restrict__ out)
{
    extern __shared__ char smem_raw[];
    Smem* s = reinterpret_cast<Smem*>(smem_raw);
    const int tid = threadIdx.x;
    const int bk = blockIdx.x / (Ll / NG);
    const int lg = blockIdx.x % (Ll / NG);
    const int b  = bk >> 4;
    const int k  = bk & 15;
    const int l0 = lg * NG;

    // ---- load h and convert to bf16 hi/lo ----
    const float* xb = x + ((size_t)b * Cc * Nn) * (Kk * Ll) + (size_t)k * Ll + l0;
    for (int i2 = tid; i2 < Cc * Nn; i2 += NTHREADS) {
        int c = i2 >> 5, n = i2 & 31;
        float2 v = *reinterpret_cast<const float2*>(xb + ((size_t)c * Nn + n) * (Kk * Ll));
        float vv[2] = {v.x, v.y};
        #pragma unroll
        for (int gp = 0; gp < NG; gp++) {
            int o = (gp * Nn + n) * KP + c;
            __nv_bfloat16 hi = __float2bfloat16(vv[gp]);
            s->hhi[o] = hi;
            s->hlo[o] = __float2bfloat16(vv[gp] - __bfloat162float(hi));
        }
    }
    for (int e = tid; e < Ee; e += NTHREADS) s->csrPack[e] = g_csr[e];
    if (tid < Nn) {
        s->rdeg[tid] = g_rdeg[tid];
        s->roff[tid] = g_roff[tid];
        s->perm[tid] = g_perm[tid];
    }

    for (int layer = 0; layer < 2; layer++) {
        __syncthreads();

        // ---- stage weights: bulk contiguous copy ----
        {
            const uint4* wsrc = reinterpret_cast<const uint4*>(g_w[layer]);
            uint4* wdst = reinterpret_cast<uint4*>(s->w);
            #pragma unroll
            for (int t = tid; t < (2 * 2 * Cc * KP * 2) / 16; t += NTHREADS)
                wdst[t] = wsrc[t];
            if (tid < 5 * Cc) s->vecs[tid] = g_vec[layer][tid];
        }
        __syncthreads();

        // ---- tensor-core GEMM via ldmatrix (hi*Whi + hi*Wlo + lo*Whi) ----
        {
            const int w    = tid >> 5;
            const int lane = tid & 31;
            const int gID  = lane >> 2;
            const int tg   = lane & 3;
            const int mat  = w >> 3;           // 0 -> xl, 1 -> xr
            const int mt   = (w >> 1) & 3;
            const int nh   = w & 1;
            const int lr   = lane & 7;
            const int seg  = lane >> 3;
            const int rowA  = mt * 16 + (seg & 1) * 8 + lr;
            const int kOffA = (seg >> 1) * 8;
            const int colB0 = nh * 32 + (seg >> 1) * 8 + lr;
            const int kOffB = (seg & 1) * 8;

            const unsigned hhiB = cvta_s(s->hhi);
            const unsigned hloB = cvta_s(s->hlo);
            const unsigned whiB = cvta_s(s->w[0][mat]);
            const unsigned wloB = cvta_s(s->w[1][mat]);
            const float* bias = s->vecs + mat * Cc;
            float* dst        = mat ? (float*)s->xr : (float*)s->xl;

            float acc[4][4];
            #pragma unroll
            for (int j = 0; j < 4; j++)
                #pragma unroll
                for (int q = 0; q < 4; q++) acc[j][q] = 0.f;

            #pragma unroll
            for (int kk = 0; kk < 4; kk++) {
                const int ka = kk * 16;
                unsigned ah[4], al[4];
                ldsm_x4(ah, hhiB + (unsigned)(rowA * KP + ka + kOffA) * 2);
                ldsm_x4(al, hloB + (unsigned)(rowA * KP + ka + kOffA) * 2);
                #pragma unroll
                for (int jp = 0; jp < 2; jp++) {
                    const int cB = colB0 + jp * 16;
                    unsigned bh[4], blo[4];
                    ldsm_x4(bh,  whiB + (unsigned)(cB * KP + ka + kOffB) * 2);
                    ldsm_x4(blo, wloB + (unsigned)(cB * KP + ka + kOffB) * 2);
                    mma16816(acc[jp * 2],     ah, bh);
                    mma16816(acc[jp * 2],     ah, blo);
                    mma16816(acc[jp * 2],     al, bh);
                    mma16816(acc[jp * 2 + 1], ah, bh + 2);
                    mma16816(acc[jp * 2 + 1], ah, blo + 2);
                    mma16816(acc[jp * 2 + 1], al, bh + 2);
                }
            }
            #pragma unroll
            for (int j = 0; j < 4; j++) {
                const int col = nh * 32 + j * 8 + tg * 2;
                float2 bv = *reinterpret_cast<const float2*>(bias + col);
                int r0 = mt * 16 + gID, r1 = r0 + 8;
                float2 v0 = make_float2(acc[j][0] + bv.x, acc[j][1] + bv.y);
                float2 v1 = make_float2(acc[j][2] + bv.x, acc[j][3] + bv.y);
                *reinterpret_cast<float2*>(dst + (size_t)(r0 >> 5) * (Nn * XP) + (r0 & 31) * XP + col) = v0;
                *reinterpret_cast<float2*>(dst + (size_t)(r1 >> 5) * (Nn * XP) + (r1 & 31) * XP + col) = v1;
            }
        }
        __syncthreads();

        // ---- FUSED scores + softmax + aggregation: thread (hq,hd,n) x both graphs ----
        {
            const int lane = tid & 31;
            const int hq = tid & 3;              // channel quarter within head
            const int hd = (tid >> 2) & 3;
            const int nr = (tid >> 4) & 31;      // sorted rank
            const int n  = s->perm[nr];
            const int base = hd * Dd + hq * 4;
            const unsigned qmask = 0xFu << (lane & 28);  // 4-lane group, shared dg
            float4 we = *reinterpret_cast<const float4*>(s->vecs + 2 * Cc + base);
            float4 at = *reinterpret_cast<const float4*>(s->vecs + 3 * Cc + base);
            float4 x0 = *reinterpret_cast<const float4*>(&s->xr[0][n * XP + base]);
            float4 x1 = *reinterpret_cast<const float4*>(&s->xr[1][n * XP + base]);
            const int dg = s->rdeg[nr], o = s->roff[nr];
            float4 ac0 = make_float4(0.f, 0.f, 0.f, 0.f);
            float4 ac1 = make_float4(0.f, 0.f, 0.f, 0.f);
            float den0 = 0.f, den1 = 0.f;
            for (int j = 0; j < dg; j++) {
                int2 ce = s->csrPack[o + j];
                float w = __int_as_float(ce.y);
                float4 a0 = *reinterpret_cast<const float4*>(&s->xl[0][ce.x + base]);
                float4 a1 = *reinterpret_cast<const float4*>(&s->xl[1][ce.x + base]);
                float z, s0 = 0.f, s1 = 0.f;
                z = a0.x + x0.x + w * we.x; z = fmaxf(z, 0.2f * z); s0 = fmaf(z, at.x, s0);
                z = a1.x + x1.x + w * we.x; z = fmaxf(z, 0.2f * z); s1 = fmaf(z, at.x, s1);
                z = a0.y + x0.y + w * we.y; z = fmaxf(z, 0.2f * z); s0 = fmaf(z, at.y, s0);
                z = a1.y + x1.y + w * we.y; z = fmaxf(z, 0.2f * z); s1 = fmaf(z, at.y, s1);
                z = a0.z + x0.z + w * we.z; z = fmaxf(z, 0.2f * z); s0 = fmaf(z, at.z, s0);
                z = a1.z + x1.z + w * we.z; z = fmaxf(z, 0.2f * z); s1 = fmaf(z, at.z, s1);
                z = a0.w + x0.w + w * we.w; z = fmaxf(z, 0.2f * z); s0 = fmaf(z, at.w, s0);
                z = a1.w + x1.w + w * we.w; z = fmaxf(z, 0.2f * z); s1 = fmaf(z, at.w, s1);
                s0 += __shfl_xor_sync(qmask, s0, 1);
                s1 += __shfl_xor_sync(qmask, s1, 1);
                s0 += __shfl_xor_sync(qmask, s0, 2);
                s1 += __shfl_xor_sync(qmask, s1, 2);
                float ex0 = __expf(s0);
                float ex1 = __expf(s1);
                den0 += ex0; den1 += ex1;
                ac0.x = fmaf(ex0, a0.x, ac0.x); ac0.y = fmaf(ex0, a0.y, ac0.y);
                ac0.z = fmaf(ex0, a0.z, ac0.z); ac0.w = fmaf(ex0, a0.w, ac0.w);
                ac1.x = fmaf(ex1, a1.x, ac1.x); ac1.y = fmaf(ex1, a1.y, ac1.y);
                ac1.z = fmaf(ex1, a1.z, ac1.z); ac1.w = fmaf(ex1, a1.w, ac1.w);
            }
            float r0 = (dg > 0) ? (1.f / den0) : 0.f;
            float r1 = (dg > 0) ? (1.f / den1) : 0.f;
            float4 bo4 = *reinterpret_cast<const float4*>(s->vecs + 4 * Cc + base);
            float v0[4] = { fmaf(ac0.x, r0, bo4.x), fmaf(ac0.y, r0, bo4.y),
                            fmaf(ac0.z, r0, bo4.z), fmaf(ac0.w, r0, bo4.w) };
            float v1[4] = { fmaf(ac1.x, r1, bo4.x), fmaf(ac1.y, r1, bo4.y),
                            fmaf(ac1.z, r1, bo4.z), fmaf(ac1.w, r1, bo4.w) };
            if (layer == 0) {
                #pragma unroll
                for (int q = 0; q < 4; q++) { v0[q] = fmaxf(v0[q], 0.f); v1[q] = fmaxf(v1[q], 0.f); }
                int o0 = n * KP + base, o1 = (Nn + n) * KP + base;   // 8B-aligned
                unsigned h0a = pack_bf16(v0[0], v0[1]), h0b = pack_bf16(v0[2], v0[3]);
                unsigned h1a = pack_bf16(v1[0], v1[1]), h1b = pack_bf16(v1[2], v1[3]);
                __nv_bfloat162* p;
                p = reinterpret_cast<__nv_bfloat162*>(&h0a);
                unsigned l0a = pack_bf16(v0[0] - __bfloat162float(p->x), v0[1] - __bfloat162float(p->y));
                p = reinterpret_cast<__nv_bfloat162*>(&h0b);
                unsigned l0b = pack_bf16(v0[2] - __bfloat162float(p->x), v0[3] - __bfloat162float(p->y));
                p = reinterpret_cast<__nv_bfloat162*>(&h1a);
                unsigned l1a = pack_bf16(v1[0] - __bfloat162float(p->x), v1[1] - __bfloat162float(p->y));
                p = reinterpret_cast<__nv_bfloat162*>(&h1b);
                unsigned l1b = pack_bf16(v1[2] - __bfloat162float(p->x), v1[3] - __bfloat162float(p->y));
                *reinterpret_cast<uint2*>(&s->hhi[o0]) = make_uint2(h0a, h0b);
                *reinterpret_cast<uint2*>(&s->hlo[o0]) = make_uint2(l0a, l0b);
                *reinterpret_cast<uint2*>(&s->hhi[o1]) = make_uint2(h1a, h1b);
                *reinterpret_cast<uint2*>(&s->hlo[o1]) = make_uint2(l1a, l1b);
            } else {
                *reinterpret_cast<float4*>(&s->hOut[0][n * OP + base]) =
                    make_float4(v0[0], v0[1], v0[2], v0[3]);
                *reinterpret_cast<float4*>(&s->hOut[1][n * OP + base]) =
                    make_float4(v1[0], v1[1], v1[2], v1[3]);
            }
        }
    }
    __syncthreads();

    // ---- write output ----
    float* ob = out + ((size_t)b * Cc * Nn) * (Kk * Ll) + (size_t)k * Ll + l0;
    for (int i2 = tid; i2 < Cc * Nn; i2 += NTHREADS) {
        int c = i2 >> 5, n = i2 & 31;
        float2 v = make_float2(s->hOut[0][n * OP + c], s->hOut[1][n * OP + c]);
        *reinterpret_cast<float2*>(ob + ((size_t)c * Nn + n) * (Kk * Ll)) = v;
    }
}

extern "C" void kernel_launch(void* const* d_in, const int* in_sizes, int n_in,
                              void* d_out, int out_size)
{
    const float* x   = (const float*)d_in[0];
    const int*   ei  = (const int*)  d_in[1];
    const float* ewg = (const float*)d_in[2];
    const float* Wl  = (const float*)d_in[3];
    const float* bl  = (const float*)d_in[4];
    const float* Wr  = (const float*)d_in[5];
    const float* br  = (const float*)d_in[6];
    const float* We  = (const float*)d_in[7];
    const float* att = (const float*)d_in[8];
    const float* bo  = (const float*)d_in[9];
    float* out = (float*)d_out;

    (void)in_sizes; (void)n_in; (void)out_size;

    gat_setup<<<64, 256>>>(ei, ewg, Wl, bl, Wr, br, We, att, bo);

    int smem = (int)sizeof(Smem);
    cudaFuncSetAttribute(gat_fused, cudaFuncAttributeMaxDynamicSharedMemorySize, smem);
    dim3 grid(Bb * Kk * (Ll / NG));   // 3072 blocks, 2 graphs each
    gat_fused<<<grid, NTHREADS, smem>>>(x, out);
}

// round 13
// speedup vs baseline: 1.1708x; 1.0972x over previous
#include <cuda_runtime.h>
#include <cuda_bf16.h>

// SpatialGNN: 2-layer GATv2, G = 6144 graphs, N=32, C=64, H=4, D=16, E=160.
// R13: (a) fused gather manually unrolled to 2 independent edges per
// iteration (peeled odd tail) -> ~1.7x chain ILP; (b) phase restructure:
// layer-0 weights staged in init, layer-1 weights staged inside layer-0's
// gather phase (w region dead there), both layers' vecs staged upfront.
// 5 barriers total (was 7).

#define Bb 16
#define Cc 64
#define Nn 32
#define Kk 16
#define Ll 24
#define Ee 160
#define Hh 4
#define Dd 16
#define NG 2
#define Mm 64         // GEMM rows = NG * Nn
#define KP 72         // bf16 row stride for h and weight tiles
#define XP 68         // fp32 row stride for xl/xr
#define OP 68         // fp32 row stride for hOut
#define NTHREADS 512
#define W_U4 2304     // uint4 count of one layer's weight block (36864 B / 16)

// ---- block-invariant precomputed state ----
__device__ __align__(16) __nv_bfloat16 g_w[2][2][2][Cc * KP]; // [layer][hi/lo][mat][co*KP+ci]
__device__ __align__(16) float g_vec[2][5 * Cc];              // [layer][bl|br|We|att|bo]
__device__ __align__(16) int2  g_csr[Ee];                     // {src*XP, ew_bits} grouped by dst (rank order)
__device__ int g_rdeg[Nn], g_roff[Nn], g_perm[Nn];            // per sorted rank

struct __align__(16) Smem {
    __nv_bfloat16 hhi[Mm * KP];
    __nv_bfloat16 hlo[Mm * KP];
    union {
        __nv_bfloat16 w[2][2][Cc * KP];   // [hi/lo][mat]
        float hOut[NG][Nn * OP];          // final-layer fp32 result (aliased)
    };
    float xl[NG][Nn * XP];
    float xr[NG][Nn * XP];
    float vecs[2][5 * Cc] __attribute__((aligned(16)));   // both layers resident
    int2  csrPack[Ee];
    int   rdeg[Nn], roff[Nn], perm[Nn];
};

__global__ void __launch_bounds__(256)
gat_setup(const int* __restrict__ ei, const float* __restrict__ ewg,
          const float* __restrict__ Wl, const float* __restrict__ blg,
          const float* __restrict__ Wr, const float* __restrict__ brg,
          const float* __restrict__ Weg, const float* __restrict__ attg,
          const float* __restrict__ bog)
{
    const int tid = threadIdx.x;
    const int gt  = blockIdx.x * 256 + tid;   // 64 blocks * 256 = 16384 = 2*2*64*64

    {
        int t = gt;
        int layer = t >> 13, mat = (t >> 12) & 1, co = (t >> 6) & 63, ci = t & 63;
        const float* W = (mat ? Wr : Wl) + layer * Cc * Cc;
        float wv = W[co * Cc + ci];
        __nv_bfloat16 hi = __float2bfloat16(wv);
        g_w[layer][0][mat][co * KP + ci] = hi;
        g_w[layer][1][mat][co * KP + ci] = __float2bfloat16(wv - __bfloat162float(hi));
    }

    if (blockIdx.x == 0) {
        __shared__ int sdst[Ee], ssrc[Ee];
        __shared__ float sew[Ee];
        __shared__ int sdeg[Nn], soff[Nn], sperm[Nn], srank[Nn];

        for (int t = tid; t < 2 * 5 * Cc; t += 256) {
            int layer = t / (5 * Cc), r = t % (5 * Cc), j = r >> 6, c = r & 63;
            const float* p = (j == 0) ? blg : (j == 1) ? brg : (j == 2) ? Weg : (j == 3) ? attg : bog;
            g_vec[layer][r] = p[layer * Cc + c];
        }
        if (tid < Ee) { ssrc[tid] = ei[tid]; sdst[tid] = ei[Ee + tid]; sew[tid] = ewg[tid]; }
        if (tid < Nn) sdeg[tid] = 0;
        __syncthreads();
        if (tid < Ee) atomicAdd(&sdeg[sdst[tid]], 1);
        __syncthreads();
        if (tid == 0) {
            for (int r = 0; r < Nn; r++) sperm[r] = r;
            for (int i = 1; i < Nn; i++) {
                int v = sperm[i], dv = sdeg[v], j = i - 1;
                while (j >= 0 && sdeg[sperm[j]] < dv) { sperm[j + 1] = sperm[j]; j--; }
                sperm[j + 1] = v;
            }
            int a = 0;
            for (int r = 0; r < Nn; r++) {
                int n = sperm[r];
                srank[n] = r;
                soff[r] = a;
                g_roff[r] = a;
                g_rdeg[r] = sdeg[n];
                g_perm[r] = n;
                a += sdeg[n];
            }
        }
        __syncthreads();
        if (tid < Ee) {
            int n = sdst[tid], rank = 0;
            for (int e2 = 0; e2 < tid; e2++) rank += (sdst[e2] == n);
            g_csr[soff[srank[n]] + rank] = make_int2(ssrc[tid] * XP, __float_as_int(sew[tid]));
        }
    }
}

__device__ __forceinline__ void mma16816(float* d, const unsigned* a, const unsigned* b) {
    asm volatile(
        "mma.sync.aligned.m16n8k16.row.col.f32.bf16.bf16.f32 "
        "{%0,%1,%2,%3}, {%4,%5,%6,%7}, {%8,%9}, {%0,%1,%2,%3};"
        : "+f"(d[0]), "+f"(d[1]), "+f"(d[2]), "+f"(d[3])
        : "r"(a[0]), "r"(a[1]), "r"(a[2]), "r"(a[3]), "r"(b[0]), "r"(b[1]));
}

__device__ __forceinline__ void ldsm_x4(unsigned* r, unsigned addr) {
    asm volatile("ldmatrix.sync.aligned.m8n8.x4.shared.b16 {%0,%1,%2,%3}, [%4];"
        : "=r"(r[0]), "=r"(r[1]), "=r"(r[2]), "=r"(r[3]) : "r"(addr));
}

__device__ __forceinline__ unsigned cvta_s(const void* p) {
    return (unsigned)__cvta_generic_to_shared(p);
}

__device__ __forceinline__ unsigned pack_bf16(float lo, float hi) {
    __nv_bfloat162 p = __floats2bfloat162_rn(lo, hi);
    return *reinterpret_cast<unsigned*>(&p);
}

__global__ void __launch_bounds__(NTHREADS, 2)
gat_fused(const float* __restrict__ x, float* __restrict__ out)
{
    extern __shared__ char smem_raw[];
    Smem* s = reinterpret_cast<Smem*>(smem_raw);
    const int tid = threadIdx.x;
    const int bk = blockIdx.x / (Ll / NG);
    const int lg = blockIdx.x % (Ll / NG);
    const int b  = bk >> 4;
    const int k  = bk & 15;
    const int l0 = lg * NG;

    // ---- init: h -> bf16 hi/lo, topology, BOTH vec sets, layer-0 weights ----
    const float* xb = x + ((size_t)b * Cc * Nn) * (Kk * Ll) + (size_t)k * Ll + l0;
    for (int i2 = tid; i2 < Cc * Nn; i2 += NTHREADS) {
        int c = i2 >> 5, n = i2 & 31;
        float2 v = *reinterpret_cast<const float2*>(xb + ((size_t)c * Nn + n) * (Kk * Ll));
        float vv[2] = {v.x, v.y};
        #pragma unroll
        for (int gp = 0; gp < NG; gp++) {
            int o = (gp * Nn + n) * KP + c;
            __nv_bfloat16 hi = __float2bfloat16(vv[gp]);
            s->hhi[o] = hi;
            s->hlo[o] = __float2bfloat16(vv[gp] - __bfloat162float(hi));
        }
    }
    for (int e = tid; e < Ee; e += NTHREADS) s->csrPack[e] = g_csr[e];
    if (tid < Nn) {
        s->rdeg[tid] = g_rdeg[tid];
        s->roff[tid] = g_roff[tid];
        s->perm[tid] = g_perm[tid];
    }
    for (int t = tid; t < 2 * 5 * Cc; t += NTHREADS)
        s->vecs[t / (5 * Cc)][t % (5 * Cc)] = g_vec[t / (5 * Cc)][t % (5 * Cc)];
    {
        const uint4* wsrc = reinterpret_cast<const uint4*>(g_w[0]);
        uint4* wdst = reinterpret_cast<uint4*>(s->w);
        #pragma unroll
        for (int t = tid; t < W_U4; t += NTHREADS) wdst[t] = wsrc[t];
    }
    __syncthreads();

    #pragma unroll
    for (int layer = 0; layer < 2; layer++) {
        // ---- tensor-core GEMM via ldmatrix (hi*Whi + hi*Wlo + lo*Whi) ----
        {
            const int w    = tid >> 5;
            const int lane = tid & 31;
            const int gID  = lane >> 2;
            const int tg   = lane & 3;
            const int mat  = w >> 3;           // 0 -> xl, 1 -> xr
            const int mt   = (w >> 1) & 3;
            const int nh   = w & 1;
            const int lr   = lane & 7;
            const int seg  = lane >> 3;
            const int rowA  = mt * 16 + (seg & 1) * 8 + lr;
            const int kOffA = (seg >> 1) * 8;
            const int colB0 = nh * 32 + (seg >> 1) * 8 + lr;
            const int kOffB = (seg & 1) * 8;

            const unsigned hhiB = cvta_s(s->hhi);
            const unsigned hloB = cvta_s(s->hlo);
            const unsigned whiB = cvta_s(s->w[0][mat]);
            const unsigned wloB = cvta_s(s->w[1][mat]);
            const float* bias = s->vecs[layer] + mat * Cc;
            float* dst        = mat ? (float*)s->xr : (float*)s->xl;

            float acc[4][4];
            #pragma unroll
            for (int j = 0; j < 4; j++)
                #pragma unroll
                for (int q = 0; q < 4; q++) acc[j][q] = 0.f;

            #pragma unroll
            for (int kk = 0; kk < 4; kk++) {
                const int ka = kk * 16;
                unsigned ah[4], al[4];
                ldsm_x4(ah, hhiB + (unsigned)(rowA * KP + ka + kOffA) * 2);
                ldsm_x4(al, hloB + (unsigned)(rowA * KP + ka + kOffA) * 2);
                #pragma unroll
                for (int jp = 0; jp < 2; jp++) {
                    const int cB = colB0 + jp * 16;
                    unsigned bh[4], blo[4];
                    ldsm_x4(bh,  whiB + (unsigned)(cB * KP + ka + kOffB) * 2);
                    ldsm_x4(blo, wloB + (unsigned)(cB * KP + ka + kOffB) * 2);
                    mma16816(acc[jp * 2],     ah, bh);
                    mma16816(acc[jp * 2],     ah, blo);
                    mma16816(acc[jp * 2],     al, bh);
                    mma16816(acc[jp * 2 + 1], ah, bh + 2);
                    mma16816(acc[jp * 2 + 1], ah, blo + 2);
                    mma16816(acc[jp * 2 + 1], al, bh + 2);
                }
            }
            #pragma unroll
            for (int j = 0; j < 4; j++) {
                const int col = nh * 32 + j * 8 + tg * 2;
                float2 bv = *reinterpret_cast<const float2*>(bias + col);
                int r0 = mt * 16 + gID, r1 = r0 + 8;
                float2 v0 = make_float2(acc[j][0] + bv.x, acc[j][1] + bv.y);
                float2 v1 = make_float2(acc[j][2] + bv.x, acc[j][3] + bv.y);
                *reinterpret_cast<float2*>(dst + (size_t)(r0 >> 5) * (Nn * XP) + (r0 & 31) * XP + col) = v0;
                *reinterpret_cast<float2*>(dst + (size_t)(r1 >> 5) * (Nn * XP) + (r1 & 31) * XP + col) = v1;
            }
        }
        __syncthreads();

        // ---- stage layer-1 weights during layer-0 gather (w region is dead) ----
        if (layer == 0) {
            const uint4* wsrc = reinterpret_cast<const uint4*>(g_w[1]);
            uint4* wdst = reinterpret_cast<uint4*>(s->w);
            #pragma unroll
            for (int t = tid; t < W_U4; t += NTHREADS) wdst[t] = wsrc[t];
        }

        // ---- FUSED scores + softmax + aggregation, 2 edges per iteration ----
        {
            const int lane = tid & 31;
            const int hq = tid & 3;
            const int hd = (tid >> 2) & 3;
            const int nr = (tid >> 4) & 31;
            const int n  = s->perm[nr];
            const int base = hd * Dd + hq * 4;
            const unsigned qmask = 0xFu << (lane & 28);
            const float* vec = s->vecs[layer];
            float4 we = *reinterpret_cast<const float4*>(vec + 2 * Cc + base);
            float4 at = *reinterpret_cast<const float4*>(vec + 3 * Cc + base);
            float4 x0 = *reinterpret_cast<const float4*>(&s->xr[0][n * XP + base]);
            float4 x1 = *reinterpret_cast<const float4*>(&s->xr[1][n * XP + base]);
            const int dg = s->rdeg[nr], o = s->roff[nr];
            float4 ac0 = make_float4(0.f, 0.f, 0.f, 0.f);
            float4 ac1 = make_float4(0.f, 0.f, 0.f, 0.f);
            float den0 = 0.f, den1 = 0.f;

            auto edge = [&](int idx) {
                int2 ce = s->csrPack[idx];
                float w = __int_as_float(ce.y);
                float4 a0 = *reinterpret_cast<const float4*>(&s->xl[0][ce.x + base]);
                float4 a1 = *reinterpret_cast<const float4*>(&s->xl[1][ce.x + base]);
                float z, s0 = 0.f, s1 = 0.f;
                z = a0.x + x0.x + w * we.x; z = fmaxf(z, 0.2f * z); s0 = fmaf(z, at.x, s0);
                z = a1.x + x1.x + w * we.x; z = fmaxf(z, 0.2f * z); s1 = fmaf(z, at.x, s1);
                z = a0.y + x0.y + w * we.y; z = fmaxf(z, 0.2f * z); s0 = fmaf(z, at.y, s0);
                z = a1.y + x1.y + w * we.y; z = fmaxf(z, 0.2f * z); s1 = fmaf(z, at.y, s1);
                z = a0.z + x0.z + w * we.z; z = fmaxf(z, 0.2f * z); s0 = fmaf(z, at.z, s0);
                z = a1.z + x1.z + w * we.z; z = fmaxf(z, 0.2f * z); s1 = fmaf(z, at.z, s1);
                z = a0.w + x0.w + w * we.w; z = fmaxf(z, 0.2f * z); s0 = fmaf(z, at.w, s0);
                z = a1.w + x1.w + w * we.w; z = fmaxf(z, 0.2f * z); s1 = fmaf(z, at.w, s1);
                s0 += __shfl_xor_sync(qmask, s0, 1);
                s1 += __shfl_xor_sync(qmask, s1, 1);
                s0 += __shfl_xor_sync(qmask, s0, 2);
                s1 += __shfl_xor_sync(qmask, s1, 2);
                float ex0 = __expf(s0);
                float ex1 = __expf(s1);
                den0 += ex0; den1 += ex1;
                ac0.x = fmaf(ex0, a0.x, ac0.x); ac0.y = fmaf(ex0, a0.y, ac0.y);
                ac0.z = fmaf(ex0, a0.z, ac0.z); ac0.w = fmaf(ex0, a0.w, ac0.w);
                ac1.x = fmaf(ex1, a1.x, ac1.x); ac1.y = fmaf(ex1, a1.y, ac1.y);
                ac1.z = fmaf(ex1, a1.z, ac1.z); ac1.w = fmaf(ex1, a1.w, ac1.w);
            };

            int j = 0;
            if (dg & 1) { edge(o); j = 1; }
            for (; j < dg; j += 2) {   // two independent edges per iteration
                edge(o + j);
                edge(o + j + 1);
            }

            float r0 = (dg > 0) ? (1.f / den0) : 0.f;
            float r1 = (dg > 0) ? (1.f / den1) : 0.f;
            float4 bo4 = *reinterpret_cast<const float4*>(vec + 4 * Cc + base);
            float v0[4] = { fmaf(ac0.x, r0, bo4.x), fmaf(ac0.y, r0, bo4.y),
                            fmaf(ac0.z, r0, bo4.z), fmaf(ac0.w, r0, bo4.w) };
            float v1[4] = { fmaf(ac1.x, r1, bo4.x), fmaf(ac1.y, r1, bo4.y),
                            fmaf(ac1.z, r1, bo4.z), fmaf(ac1.w, r1, bo4.w) };
            if (layer == 0) {
                #pragma unroll
                for (int q = 0; q < 4; q++) { v0[q] = fmaxf(v0[q], 0.f); v1[q] = fmaxf(v1[q], 0.f); }
                int o0 = n * KP + base, o1 = (Nn + n) * KP + base;   // 8B-aligned
                unsigned h0a = pack_bf16(v0[0], v0[1]), h0b = pack_bf16(v0[2], v0[3]);
                unsigned h1a = pack_bf16(v1[0], v1[1]), h1b = pack_bf16(v1[2], v1[3]);
                __nv_bfloat162* p;
                p = reinterpret_cast<__nv_bfloat162*>(&h0a);
                unsigned l0a = pack_bf16(v0[0] - __bfloat162float(p->x), v0[1] - __bfloat162float(p->y));
                p = reinterpret_cast<__nv_bfloat162*>(&h0b);
                unsigned l0b = pack_bf16(v0[2] - __bfloat162float(p->x), v0[3] - __bfloat162float(p->y));
                p = reinterpret_cast<__nv_bfloat162*>(&h1a);
                unsigned l1a = pack_bf16(v1[0] - __bfloat162float(p->x), v1[1] - __bfloat162float(p->y));
                p = reinterpret_cast<__nv_bfloat162*>(&h1b);
                unsigned l1b = pack_bf16(v1[2] - __bfloat162float(p->x), v1[3] - __bfloat162float(p->y));
                *reinterpret_cast<uint2*>(&s->hhi[o0]) = make_uint2(h0a, h0b);
                *reinterpret_cast<uint2*>(&s->hlo[o0]) = make_uint2(l0a, l0b);
                *reinterpret_cast<uint2*>(&s->hhi[o1]) = make_uint2(h1a, h1b);
                *reinterpret_cast<uint2*>(&s->hlo[o1]) = make_uint2(l1a, l1b);
            } else {
                *reinterpret_cast<float4*>(&s->hOut[0][n * OP + base]) =
                    make_float4(v0[0], v0[1], v0[2], v0[3]);
                *reinterpret_cast<float4*>(&s->hOut[1][n * OP + base]) =
                    make_float4(v1[0], v1[1], v1[2], v1[3]);
            }
        }
        __syncthreads();
    }

    // ---- write output ----
    float* ob = out + ((size_t)b * Cc * Nn) * (Kk * Ll) + (size_t)k * Ll + l0;
    for (int i2 = tid; i2 < Cc * Nn; i2 += NTHREADS) {
        int c = i2 >> 5, n = i2 & 31;
        float2 v = make_float2(s->hOut[0][n * OP + c], s->hOut[1][n * OP + c]);
        *reinterpret_cast<float2*>(ob + ((size_t)c * Nn + n) * (Kk * Ll)) = v;
    }
}

extern "C" void kernel_launch(void* const* d_in, const int* in_sizes, int n_in,
                              void* d_out, int out_size)
{
    const float* x   = (const float*)d_in[0];
    const int*   ei  = (const int*)  d_in[1];
    const float* ewg = (const float*)d_in[2];
    const float* Wl  = (const float*)d_in[3];
    const float* bl  = (const float*)d_in[4];
    const float* Wr  = (const float*)d_in[5];
    const float* br  = (const float*)d_in[6];
    const float* We  = (const float*)d_in[7];
    const float* att = (const float*)d_in[8];
    const float* bo  = (const float*)d_in[9];
    float* out = (float*)d_out;

    (void)in_sizes; (void)n_in; (void)out_size;

    gat_setup<<<64, 256>>>(ei, ewg, Wl, bl, Wr, br, We, att, bo);

    int smem = (int)sizeof(Smem);
    cudaFuncSetAttribute(gat_fused, cudaFuncAttributeMaxDynamicSharedMemorySize, smem);
    dim3 grid(Bb * Kk * (Ll / NG));   // 3072 blocks, 2 graphs each
    gat_fused<<<grid, NTHREADS, smem>>>(x, out);
}

// round 14
// speedup vs baseline: 1.2451x; 1.0635x over previous
#include <cuda_runtime.h>
#include <cuda_bf16.h>

// SpatialGNN: 2-layer GATv2, G = 6144 graphs, N=32, C=64, H=4, D=16, E=160.
// R14: (a) CSR entries software-pipelined one pair ahead in the fused gather;
// (b) log2e folded into att at setup, exp via ex2.approx (one fewer mul in
// the per-edge chain); (c) layer-1 result written straight to global from
// registers (hOut smem round-trip, output loop, and final barrier deleted).

#define Bb 16
#define Cc 64
#define Nn 32
#define Kk 16
#define Ll 24
#define Ee 160
#define Hh 4
#define Dd 16
#define NG 2
#define Mm 64         // GEMM rows = NG * Nn
#define KP 72         // bf16 row stride for h and weight tiles
#define XP 68         // fp32 row stride for xl/xr
#define NTHREADS 512
#define W_U4 2304     // uint4 count of one layer's weight block (36864 B / 16)

// ---- block-invariant precomputed state ----
__device__ __align__(16) __nv_bfloat16 g_w[2][2][2][Cc * KP]; // [layer][hi/lo][mat][co*KP+ci]
__device__ __align__(16) float g_vec[2][5 * Cc];              // [layer][bl|br|We|att*log2e|bo]
__device__ __align__(16) int2  g_csr[Ee];                     // {src*XP, ew_bits} grouped by dst (rank order)
__device__ int g_rdeg[Nn], g_roff[Nn], g_perm[Nn];            // per sorted rank

struct __align__(16) Smem {
    __nv_bfloat16 hhi[Mm * KP];
    __nv_bfloat16 hlo[Mm * KP];
    __nv_bfloat16 w[2][2][Cc * KP];       // [hi/lo][mat]
    float xl[NG][Nn * XP];
    float xr[NG][Nn * XP];
    float vecs[2][5 * Cc] __attribute__((aligned(16)));   // both layers resident
    int2  csrPack[Ee];
    int   rdeg[Nn], roff[Nn], perm[Nn];
};

__global__ void __launch_bounds__(256)
gat_setup(const int* __restrict__ ei, const float* __restrict__ ewg,
          const float* __restrict__ Wl, const float* __restrict__ blg,
          const float* __restrict__ Wr, const float* __restrict__ brg,
          const float* __restrict__ Weg, const float* __restrict__ attg,
          const float* __restrict__ bog)
{
    const int tid = threadIdx.x;
    const int gt  = blockIdx.x * 256 + tid;   // 64 blocks * 256 = 16384 = 2*2*64*64

    {
        int t = gt;
        int layer = t >> 13, mat = (t >> 12) & 1, co = (t >> 6) & 63, ci = t & 63;
        const float* W = (mat ? Wr : Wl) + layer * Cc * Cc;
        float wv = W[co * Cc + ci];
        __nv_bfloat16 hi = __float2bfloat16(wv);
        g_w[layer][0][mat][co * KP + ci] = hi;
        g_w[layer][1][mat][co * KP + ci] = __float2bfloat16(wv - __bfloat162float(hi));
    }

    if (blockIdx.x == 0) {
        __shared__ int sdst[Ee], ssrc[Ee];
        __shared__ float sew[Ee];
        __shared__ int sdeg[Nn], soff[Nn], sperm[Nn], srank[Nn];

        for (int t = tid; t < 2 * 5 * Cc; t += 256) {
            int layer = t / (5 * Cc), r = t % (5 * Cc), j = r >> 6, c = r & 63;
            const float* p = (j == 0) ? blg : (j == 1) ? brg : (j == 2) ? Weg : (j == 3) ? attg : bog;
            float v = p[layer * Cc + c];
            if (j == 3) v *= 1.4426950408889634f;   // att * log2(e) -> ex2
            g_vec[layer][r] = v;
        }
        if (tid < Ee) { ssrc[tid] = ei[tid]; sdst[tid] = ei[Ee + tid]; sew[tid] = ewg[tid]; }
        if (tid < Nn) sdeg[tid] = 0;
        __syncthreads();
        if (tid < Ee) atomicAdd(&sdeg[sdst[tid]], 1);
        __syncthreads();
        if (tid == 0) {
            for (int r = 0; r < Nn; r++) sperm[r] = r;
            for (int i = 1; i < Nn; i++) {
                int v = sperm[i], dv = sdeg[v], j = i - 1;
                while (j >= 0 && sdeg[sperm[j]] < dv) { sperm[j + 1] = sperm[j]; j--; }
                sperm[j + 1] = v;
            }
            int a = 0;
            for (int r = 0; r < Nn; r++) {
                int n = sperm[r];
                srank[n] = r;
                soff[r] = a;
                g_roff[r] = a;
                g_rdeg[r] = sdeg[n];
                g_perm[r] = n;
                a += sdeg[n];
            }
        }
        __syncthreads();
        if (tid < Ee) {
            int n = sdst[tid], rank = 0;
            for (int e2 = 0; e2 < tid; e2++) rank += (sdst[e2] == n);
            g_csr[soff[srank[n]] + rank] = make_int2(ssrc[tid] * XP, __float_as_int(sew[tid]));
        }
    }
}

__device__ __forceinline__ void mma16816(float* d, const unsigned* a, const unsigned* b) {
    asm volatile(
        "mma.sync.aligned.m16n8k16.row.col.f32.bf16.bf16.f32 "
        "{%0,%1,%2,%3}, {%4,%5,%6,%7}, {%8,%9}, {%0,%1,%2,%3};"
        : "+f"(d[0]), "+f"(d[1]), "+f"(d[2]), "+f"(d[3])
        : "r"(a[0]), "r"(a[1]), "r"(a[2]), "r"(a[3]), "r"(b[0]), "r"(b[1]));
}

__device__ __forceinline__ void ldsm_x4(unsigned* r, unsigned addr) {
    asm volatile("ldmatrix.sync.aligned.m8n8.x4.shared.b16 {%0,%1,%2,%3}, [%4];"
        : "=r"(r[0]), "=r"(r[1]), "=r"(r[2]), "=r"(r[3]) : "r"(addr));
}

__device__ __forceinline__ unsigned cvta_s(const void* p) {
    return (unsigned)__cvta_generic_to_shared(p);
}

__device__ __forceinline__ unsigned pack_bf16(float lo, float hi) {
    __nv_bfloat162 p = __floats2bfloat162_rn(lo, hi);
    return *reinterpret_cast<unsigned*>(&p);
}

__device__ __forceinline__ float ex2(float v) {
    float r;
    asm("ex2.approx.f32 %0, %1;" : "=f"(r) : "f"(v));
    return r;
}

__global__ void __launch_bounds__(NTHREADS, 2)
gat_fused(const float* __restrict__ x, float* __restrict__ out)
{
    extern __shared__ char smem_raw[];
    Smem* s = reinterpret_cast<Smem*>(smem_raw);
    const int tid = threadIdx.x;
    const int bk = blockIdx.x / (Ll / NG);
    const int lg = blockIdx.x % (Ll / NG);
    const int b  = bk >> 4;
    const int k  = bk & 15;
    const int l0 = lg * NG;
    const size_t gbase = ((size_t)b * Cc * Nn) * (Kk * Ll) + (size_t)k * Ll + l0;

    // ---- init: h -> bf16 hi/lo, topology, both vec sets, layer-0 weights ----
    const float* xb = x + gbase;
    for (int i2 = tid; i2 < Cc * Nn; i2 += NTHREADS) {
        int c = i2 >> 5, n = i2 & 31;
        float2 v = *reinterpret_cast<const float2*>(xb + ((size_t)c * Nn + n) * (Kk * Ll));
        float vv[2] = {v.x, v.y};
        #pragma unroll
        for (int gp = 0; gp < NG; gp++) {
            int o = (gp * Nn + n) * KP + c;
            __nv_bfloat16 hi = __float2bfloat16(vv[gp]);
            s->hhi[o] = hi;
            s->hlo[o] = __float2bfloat16(vv[gp] - __bfloat162float(hi));
        }
    }
    for (int e = tid; e < Ee; e += NTHREADS) s->csrPack[e] = g_csr[e];
    if (tid < Nn) {
        s->rdeg[tid] = g_rdeg[tid];
        s->roff[tid] = g_roff[tid];
        s->perm[tid] = g_perm[tid];
    }
    for (int t = tid; t < 2 * 5 * Cc; t += NTHREADS)
        s->vecs[t / (5 * Cc)][t % (5 * Cc)] = g_vec[t / (5 * Cc)][t % (5 * Cc)];
    {
        const uint4* wsrc = reinterpret_cast<const uint4*>(g_w[0]);
        uint4* wdst = reinterpret_cast<uint4*>(s->w);
        #pragma unroll
        for (int t = tid; t < W_U4; t += NTHREADS) wdst[t] = wsrc[t];
    }
    __syncthreads();

    #pragma unroll
    for (int layer = 0; layer < 2; layer++) {
        // ---- tensor-core GEMM via ldmatrix (hi*Whi + hi*Wlo + lo*Whi) ----
        {
            const int w    = tid >> 5;
            const int lane = tid & 31;
            const int gID  = lane >> 2;
            const int tg   = lane & 3;
            const int mat  = w >> 3;           // 0 -> xl, 1 -> xr
            const int mt   = (w >> 1) & 3;
            const int nh   = w & 1;
            const int lr   = lane & 7;
            const int seg  = lane >> 3;
            const int rowA  = mt * 16 + (seg & 1) * 8 + lr;
            const int kOffA = (seg >> 1) * 8;
            const int colB0 = nh * 32 + (seg >> 1) * 8 + lr;
            const int kOffB = (seg & 1) * 8;

            const unsigned hhiB = cvta_s(s->hhi);
            const unsigned hloB = cvta_s(s->hlo);
            const unsigned whiB = cvta_s(s->w[0][mat]);
            const unsigned wloB = cvta_s(s->w[1][mat]);
            const float* bias = s->vecs[layer] + mat * Cc;
            float* dst        = mat ? (float*)s->xr : (float*)s->xl;

            float acc[4][4];
            #pragma unroll
            for (int j = 0; j < 4; j++)
                #pragma unroll
                for (int q = 0; q < 4; q++) acc[j][q] = 0.f;

            #pragma unroll
            for (int kk = 0; kk < 4; kk++) {
                const int ka = kk * 16;
                unsigned ah[4], al[4];
                ldsm_x4(ah, hhiB + (unsigned)(rowA * KP + ka + kOffA) * 2);
                ldsm_x4(al, hloB + (unsigned)(rowA * KP + ka + kOffA) * 2);
                #pragma unroll
                for (int jp = 0; jp < 2; jp++) {
                    const int cB = colB0 + jp * 16;
                    unsigned bh[4], blo[4];
                    ldsm_x4(bh,  whiB + (unsigned)(cB * KP + ka + kOffB) * 2);
                    ldsm_x4(blo, wloB + (unsigned)(cB * KP + ka + kOffB) * 2);
                    mma16816(acc[jp * 2],     ah, bh);
                    mma16816(acc[jp * 2],     ah, blo);
                    mma16816(acc[jp * 2],     al, bh);
                    mma16816(acc[jp * 2 + 1], ah, bh + 2);
                    mma16816(acc[jp * 2 + 1], ah, blo + 2);
                    mma16816(acc[jp * 2 + 1], al, bh + 2);
                }
            }
            #pragma unroll
            for (int j = 0; j < 4; j++) {
                const int col = nh * 32 + j * 8 + tg * 2;
                float2 bv = *reinterpret_cast<const float2*>(bias + col);
                int r0 = mt * 16 + gID, r1 = r0 + 8;
                float2 v0 = make_float2(acc[j][0] + bv.x, acc[j][1] + bv.y);
                float2 v1 = make_float2(acc[j][2] + bv.x, acc[j][3] + bv.y);
                *reinterpret_cast<float2*>(dst + (size_t)(r0 >> 5) * (Nn * XP) + (r0 & 31) * XP + col) = v0;
                *reinterpret_cast<float2*>(dst + (size_t)(r1 >> 5) * (Nn * XP) + (r1 & 31) * XP + col) = v1;
            }
        }
        __syncthreads();

        // ---- stage layer-1 weights during layer-0 gather (w needed next layer) ----
        if (layer == 0) {
            const uint4* wsrc = reinterpret_cast<const uint4*>(g_w[1]);
            uint4* wdst = reinterpret_cast<uint4*>(s->w);
            #pragma unroll
            for (int t = tid; t < W_U4; t += NTHREADS) wdst[t] = wsrc[t];
        }

        // ---- FUSED scores + softmax + aggregation, 2 edges/iter, csr prefetch ----
        {
            const int lane = tid & 31;
            const int hq = tid & 3;
            const int hd = (tid >> 2) & 3;
            const int nr = (tid >> 4) & 31;
            const int n  = s->perm[nr];
            const int base = hd * Dd + hq * 4;
            const unsigned qmask = 0xFu << (lane & 28);
            const float* vec = s->vecs[layer];
            float4 we = *reinterpret_cast<const float4*>(vec + 2 * Cc + base);
            float4 at = *reinterpret_cast<const float4*>(vec + 3 * Cc + base);
            float4 x0 = *reinterpret_cast<const float4*>(&s->xr[0][n * XP + base]);
            float4 x1 = *reinterpret_cast<const float4*>(&s->xr[1][n * XP + base]);
            const int dg = s->rdeg[nr], o = s->roff[nr];
            float4 ac0 = make_float4(0.f, 0.f, 0.f, 0.f);
            float4 ac1 = make_float4(0.f, 0.f, 0.f, 0.f);
            float den0 = 0.f, den1 = 0.f;

            auto edgeC = [&](int2 ce) {
                float w = __int_as_float(ce.y);
                float4 a0 = *reinterpret_cast<const float4*>(&s->xl[0][ce.x + base]);
                float4 a1 = *reinterpret_cast<const float4*>(&s->xl[1][ce.x + base]);
                float z, s0 = 0.f, s1 = 0.f;
                z = a0.x + x0.x + w * we.x; z = fmaxf(z, 0.2f * z); s0 = fmaf(z, at.x, s0);
                z = a1.x + x1.x + w * we.x; z = fmaxf(z, 0.2f * z); s1 = fmaf(z, at.x, s1);
                z = a0.y + x0.y + w * we.y; z = fmaxf(z, 0.2f * z); s0 = fmaf(z, at.y, s0);
                z = a1.y + x1.y + w * we.y; z = fmaxf(z, 0.2f * z); s1 = fmaf(z, at.y, s1);
                z = a0.z + x0.z + w * we.z; z = fmaxf(z, 0.2f * z); s0 = fmaf(z, at.z, s0);
                z = a1.z + x1.z + w * we.z; z = fmaxf(z, 0.2f * z); s1 = fmaf(z, at.z, s1);
                z = a0.w + x0.w + w * we.w; z = fmaxf(z, 0.2f * z); s0 = fmaf(z, at.w, s0);
                z = a1.w + x1.w + w * we.w; z = fmaxf(z, 0.2f * z); s1 = fmaf(z, at.w, s1);
                s0 += __shfl_xor_sync(qmask, s0, 1);
                s1 += __shfl_xor_sync(qmask, s1, 1);
                s0 += __shfl_xor_sync(qmask, s0, 2);
                s1 += __shfl_xor_sync(qmask, s1, 2);
                float ex0 = ex2(s0);     // att pre-scaled by log2(e)
                float ex1 = ex2(s1);
                den0 += ex0; den1 += ex1;
                ac0.x = fmaf(ex0, a0.x, ac0.x); ac0.y = fmaf(ex0, a0.y, ac0.y);
                ac0.z = fmaf(ex0, a0.z, ac0.z); ac0.w = fmaf(ex0, a0.w, ac0.w);
                ac1.x = fmaf(ex1, a1.x, ac1.x); ac1.y = fmaf(ex1, a1.y, ac1.y);
                ac1.z = fmaf(ex1, a1.z, ac1.z); ac1.w = fmaf(ex1, a1.w, ac1.w);
            };

            int j = 0;
            if (dg & 1) { edgeC(s->csrPack[o]); j = 1; }
            if (j < dg) {
                int2 c0 = s->csrPack[o + j];
                int2 c1 = s->csrPack[o + j + 1];
                for (; j + 2 < dg; j += 2) {
                    int2 p0 = s->csrPack[o + j + 2];   // prefetch next pair
                    int2 p1 = s->csrPack[o + j + 3];
                    edgeC(c0);
                    edgeC(c1);
                    c0 = p0; c1 = p1;
                }
                edgeC(c0);
                edgeC(c1);
            }

            float r0 = (dg > 0) ? (1.f / den0) : 0.f;
            float r1 = (dg > 0) ? (1.f / den1) : 0.f;
            float4 bo4 = *reinterpret_cast<const float4*>(vec + 4 * Cc + base);
            float v0[4] = { fmaf(ac0.x, r0, bo4.x), fmaf(ac0.y, r0, bo4.y),
                            fmaf(ac0.z, r0, bo4.z), fmaf(ac0.w, r0, bo4.w) };
            float v1[4] = { fmaf(ac1.x, r1, bo4.x), fmaf(ac1.y, r1, bo4.y),
                            fmaf(ac1.z, r1, bo4.z), fmaf(ac1.w, r1, bo4.w) };
            if (layer == 0) {
                #pragma unroll
                for (int q = 0; q < 4; q++) { v0[q] = fmaxf(v0[q], 0.f); v1[q] = fmaxf(v1[q], 0.f); }
                int o0 = n * KP + base, o1 = (Nn + n) * KP + base;   // 8B-aligned
                unsigned h0a = pack_bf16(v0[0], v0[1]), h0b = pack_bf16(v0[2], v0[3]);
                unsigned h1a = pack_bf16(v1[0], v1[1]), h1b = pack_bf16(v1[2], v1[3]);
                __nv_bfloat162* p;
                p = reinterpret_cast<__nv_bfloat162*>(&h0a);
                unsigned l0a = pack_bf16(v0[0] - __bfloat162float(p->x), v0[1] - __bfloat162float(p->y));
                p = reinterpret_cast<__nv_bfloat162*>(&h0b);
                unsigned l0b = pack_bf16(v0[2] - __bfloat162float(p->x), v0[3] - __bfloat162float(p->y));
                p = reinterpret_cast<__nv_bfloat162*>(&h1a);
                unsigned l1a = pack_bf16(v1[0] - __bfloat162float(p->x), v1[1] - __bfloat162float(p->y));
                p = reinterpret_cast<__nv_bfloat162*>(&h1b);
                unsigned l1b = pack_bf16(v1[2] - __bfloat162float(p->x), v1[3] - __bfloat162float(p->y));
                *reinterpret_cast<uint2*>(&s->hhi[o0]) = make_uint2(h0a, h0b);
                *reinterpret_cast<uint2*>(&s->hlo[o0]) = make_uint2(l0a, l0b);
                *reinterpret_cast<uint2*>(&s->hhi[o1]) = make_uint2(h1a, h1b);
                *reinterpret_cast<uint2*>(&s->hlo[o1]) = make_uint2(l1a, l1b);
            } else {
                // direct global write: out[b, base+q, n, k, l0 + {0,1}]
                float* ob = out + gbase;
                #pragma unroll
                for (int q = 0; q < 4; q++) {
                    *reinterpret_cast<float2*>(ob + (size_t)((base + q) * Nn + n) * (Kk * Ll)) =
                        make_float2(v0[q], v1[q]);
                }
            }
        }
        if (layer == 0) __syncthreads();
    }
}

extern "C" void kernel_launch(void* const* d_in, const int* in_sizes, int n_in,
                              void* d_out, int out_size)
{
    const float* x   = (const float*)d_in[0];
    const int*   ei  = (const int*)  d_in[1];
    const float* ewg = (const float*)d_in[2];
    const float* Wl  = (const float*)d_in[3];
    const float* bl  = (const float*)d_in[4];
    const float* Wr  = (const float*)d_in[5];
    const float* br  = (const float*)d_in[6];
    const float* We  = (const float*)d_in[7];
    const float* att = (const float*)d_in[8];
    const float* bo  = (const float*)d_in[9];
    float* out = (float*)d_out;

    (void)in_sizes; (void)n_in; (void)out_size;

    gat_setup<<<64, 256>>>(ei, ewg, Wl, bl, Wr, br, We, att, bo);

    int smem = (int)sizeof(Smem);
    cudaFuncSetAttribute(gat_fused, cudaFuncAttributeMaxDynamicSharedMemorySize, smem);
    dim3 grid(Bb * Kk * (Ll / NG));   // 3072 blocks, 2 graphs each
    gat_fused<<<grid, NTHREADS, smem>>>(x, out);
}